// round 12
// baseline (speedup 1.0000x reference)
#include <cuda_runtime.h>
#include <cstdint>
#include <cstdio>

// ----------------------------------------------------------------------------
// Real spherical harmonic transform -> real part (float32 out).
//   Re X[row,m] = sum_j E[row,j] * (s*cos(2pi m j/720)),  row = b*360+k
//   out[b,n,m]  = sum_k Re X[b,k,m] * W[m,n,k]
// R12: contract uses cp.async (LDGSTS) 3-stage pipeline, 1 barrier/phase,
// dynamic smem. gemm1 unchanged from R11.
// ----------------------------------------------------------------------------

#define NTH   360
#define NLAM  720
#define NM    361
#define NB    8
#define ROWS  (NB*NTH) // 2880
#define ROWS_P 2944    // padded to multiple of 128
#define KP    368
#define MP    384

#define X_ELEMS (NB*NTH*NLAM)       // 2,073,600
#define W_ELEMS (NM*NTH*NTH)        // 46,785,600
#define OUT_ELEMS (NB*NTH*NM)       // 1,039,680 float32

__device__ float g_C  [KP * MP];        // [j][m] = s*cos(2pi m j / 720)
__device__ float g_E  [ROWS_P * KP];    // [row][j] even fold (pad rows zero)
__device__ float g_Xre[MP * ROWS_P];    // [m][row]
__device__ __align__(16) float g_zero4[4] = {0.f, 0.f, 0.f, 0.f};

// ---------------------------------------------------------------- ptx helpers
__device__ __forceinline__ uint32_t smem_u32(const void* p) {
    uint32_t a;
    asm("{ .reg .u64 t; cvta.to.shared.u64 t, %1; cvt.u32.u64 %0, t; }"
        : "=r"(a) : "l"(p));
    return a;
}
#define CP_ASYNC16(dst, src) \
    asm volatile("cp.async.cg.shared.global [%0], [%1], 16;" \
                 :: "r"(dst), "l"(src) : "memory")
#define CP_COMMIT()  asm volatile("cp.async.commit_group;" ::: "memory")
#define CP_WAIT1()   asm volatile("cp.async.wait_group 1;" ::: "memory")

// ---------------------------------------------------------------- build table
__global__ void k_build_B() {
    int l = blockIdx.x;          // 0..367
    int m = threadIdx.x;         // 0..383
    float vc = 0.f;
    if (l <= 360) {
        int p = (l * m) % 720;
        float c = cospif((float)p * (1.0f / 360.0f));
        vc = 0.008726646259971648f * c;      // 2*pi/720
    }
    g_C[l * MP + m] = vc;
}

// ---------------------------------------------------------------- fold E
__global__ void k_fold(const float* __restrict__ x) {
    int idx = blockIdx.x * blockDim.x + threadIdx.x;
    if (idx >= ROWS_P * KP) return;
    int r = idx / KP;
    int j = idx - r * KP;
    float e = 0.f;
    if (r < ROWS && j <= 360) {
        const float* xr = x + r * NLAM;
        if (j == 0)        e = xr[0];
        else if (j == 360) e = xr[360];
        else               e = xr[j] + xr[NLAM - j];
    }
    g_E[idx] = e;
}

// ---------------------------------------------------------------- GEMM1 (DFT)
// Xre[row,m] = sum_j E[row,j] * C[j,m].  BM=128, BN=64, BK=16, 256 threads.
#define EPAD 132
#define CPAD 68
__global__ void __launch_bounds__(256) k_gemm1() {
    __shared__ __align__(16) float sE[16 * EPAD];   // [kk][row(128)]
    __shared__ __align__(16) float sC[16 * CPAD];   // [kk][m(64)]

    const int tid = threadIdx.x;
    const int ty  = tid >> 4;         // 0..15 -> rows ty*8 .. ty*8+7
    const int tx  = tid & 15;         // 0..15 -> m tx*4 .. tx*4+3
    const int m0   = blockIdx.x * 64;
    const int row0 = blockIdx.y * 128;

    float acc[8][4];
#pragma unroll
    for (int i = 0; i < 8; ++i)
#pragma unroll
        for (int j = 0; j < 4; ++j) acc[i][j] = 0.f;

    for (int k0 = 0; k0 < KP; k0 += 16) {
#pragma unroll
        for (int t = 0; t < 2; ++t) {
            int i = tid + t * 256;        // 0..511
            int r = i >> 2;               // 0..127
            int q = i & 3;
            float4 v = *reinterpret_cast<const float4*>(
                &g_E[(row0 + r) * KP + k0 + 4 * q]);
            sE[(4 * q + 0) * EPAD + r] = v.x;
            sE[(4 * q + 1) * EPAD + r] = v.y;
            sE[(4 * q + 2) * EPAD + r] = v.z;
            sE[(4 * q + 3) * EPAD + r] = v.w;
        }
        {
            int kk = tid >> 4;
            int q  = tid & 15;
            float4 v = *reinterpret_cast<const float4*>(
                &g_C[(k0 + kk) * MP + m0 + 4 * q]);
            *reinterpret_cast<float4*>(&sC[kk * CPAD + 4 * q]) = v;
        }
        __syncthreads();
#pragma unroll
        for (int kk = 0; kk < 16; ++kk) {
            float4 e0 = *reinterpret_cast<const float4*>(&sE[kk * EPAD + ty * 8]);
            float4 e1 = *reinterpret_cast<const float4*>(&sE[kk * EPAD + ty * 8 + 4]);
            float4 c  = *reinterpret_cast<const float4*>(&sC[kk * CPAD + tx * 4]);
            float e[8] = {e0.x, e0.y, e0.z, e0.w, e1.x, e1.y, e1.z, e1.w};
            float cv[4] = {c.x, c.y, c.z, c.w};
#pragma unroll
            for (int i = 0; i < 8; ++i)
#pragma unroll
                for (int j = 0; j < 4; ++j)
                    acc[i][j] = fmaf(e[i], cv[j], acc[i][j]);
        }
        __syncthreads();
    }
#pragma unroll
    for (int j = 0; j < 4; ++j) {
        int m = m0 + tx * 4 + j;
        float4 v0 = make_float4(acc[0][j], acc[1][j], acc[2][j], acc[3][j]);
        float4 v1 = make_float4(acc[4][j], acc[5][j], acc[6][j], acc[7][j]);
        *reinterpret_cast<float4*>(&g_Xre[m * ROWS_P + row0 + ty * 8])     = v0;
        *reinterpret_cast<float4*>(&g_Xre[m * ROWS_P + row0 + ty * 8 + 4]) = v1;
    }
}

// ---------------------------------------------------------------- contraction
// Grid (361, 2): (m, n-half). 192 threads, thread t owns n=t (<180), 8 b.
// cp.async 3-stage pipeline over W chunks of KC2 k.
#define NSPL 2
#define NPB  (NTH / NSPL)          // 180
#define KC2  16
#define WST  20                    // conflict-free for quarter-warp LDS.128
#define NPH  ((NTH + KC2 - 1) / KC2)   // 23
#define XS_F (ROWS + KC2)          // 2896 floats
#define CT_SMEM_F (XS_F + 3 * NPB * WST)   // 2896 + 10800 = 13696 floats
#define CT_SMEM_B (CT_SMEM_F * 4)          // 54784 bytes

__global__ void __launch_bounds__(192) k_contract(const float* __restrict__ W,
                                                  float* __restrict__ out) {
    extern __shared__ __align__(16) float dyn[];
    float* Xs = dyn;                       // [XS_F]
    float* Ws = dyn + XS_F;                // [3][NPB*WST]

    const int m   = blockIdx.x;
    const int ys  = blockIdx.y;
    const int tid = threadIdx.x;
    const int n   = tid;
    const bool live = (n < NPB);

    const float* Wm = W + (size_t)m * (NTH * NTH) + (size_t)ys * NPB * NTH;
    const float* Xg = g_Xre + (size_t)m * ROWS_P;

    auto issue_stage = [&](int stage, int k0) {
        float* dstbase = Ws + stage * (NPB * WST);
#pragma unroll
        for (int u = 0; u < 4; ++u) {
            int i = tid + 192 * u;
            if (i < NPB * (KC2 / 4)) {
                int nl = i >> 2;
                int k  = k0 + (i & 3) * 4;
                const void* src = (k + 4 <= NTH)
                    ? (const void*)(Wm + (size_t)nl * NTH + k)
                    : (const void*)g_zero4;
                CP_ASYNC16(smem_u32(&dstbase[nl * WST + (i & 3) * 4]), src);
            }
        }
    };

    // prologue: Xs + stage0 -> group0 ; stage1 -> group1
#pragma unroll
    for (int u = 0; u < 4; ++u) {
        int i = tid + 192 * u;
        if (i < XS_F / 4) {
            const void* src = (4 * i + 4 <= ROWS)
                ? (const void*)(Xg + 4 * i)
                : (const void*)g_zero4;
            CP_ASYNC16(smem_u32(&Xs[4 * i]), src);
        }
    }
    issue_stage(0, 0);
    CP_COMMIT();
    issue_stage(1, KC2);
    CP_COMMIT();

    float acc[8];
#pragma unroll
    for (int b = 0; b < 8; ++b) acc[b] = 0.f;

    for (int p = 0; p < NPH; ++p) {
        CP_WAIT1();                  // stage p (group p) complete
        __syncthreads();
        const float* Wb = Ws + (p % 3) * (NPB * WST);
        const int k0 = p * KC2;
        if (live) {
#pragma unroll
            for (int q = 0; q < KC2 / 4; ++q) {
                float4 wv = *reinterpret_cast<const float4*>(&Wb[n * WST + 4 * q]);
#pragma unroll
                for (int b = 0; b < 8; ++b) {
                    float4 xv = *reinterpret_cast<const float4*>(
                        &Xs[b * NTH + k0 + 4 * q]);   // warp-broadcast
                    acc[b] = fmaf(xv.x, wv.x, acc[b]);
                    acc[b] = fmaf(xv.y, wv.y, acc[b]);
                    acc[b] = fmaf(xv.z, wv.z, acc[b]);
                    acc[b] = fmaf(xv.w, wv.w, acc[b]);
                }
            }
        }
        if (p + 2 < NPH) issue_stage((p + 2) % 3, (p + 2) * KC2);
        CP_COMMIT();                 // always commit (keeps group numbering)
    }

    if (live) {
        const int ng = ys * NPB + n;
#pragma unroll
        for (int b = 0; b < 8; ++b)
            out[(size_t)(b * NTH + ng) * NM + m] = acc[b];
    }
}

// ---------------------------------------------------------------- host diag
static bool sync_check(const char* stage) {
    cudaError_t e = cudaDeviceSynchronize();
    if (e == cudaSuccess) e = cudaGetLastError();
    if (e != cudaSuccess) {
        fprintf(stderr, "[diag] stage %-10s : %s\n", stage, cudaGetErrorString(e));
        fflush(stderr);
        return false;
    }
    return true;
}

// ---------------------------------------------------------------- launch
extern "C" void kernel_launch(void* const* d_in, const int* in_sizes, int n_in,
                              void* d_out, int out_size) {
    const float* x = nullptr;
    const float* w = nullptr;
    for (int i = 0; i < n_in; ++i) {
        if (in_sizes[i] == X_ELEMS && !x) x = (const float*)d_in[i];
        else if (in_sizes[i] == W_ELEMS && !w) w = (const float*)d_in[i];
    }
    float* out = (float*)d_out;
    if (!x || !w) return;

    // opt-in >48KB dynamic smem (host attribute set; not a stream op)
    cudaFuncSetAttribute(k_contract,
                         cudaFuncAttributeMaxDynamicSharedMemorySize, CT_SMEM_B);

    cudaStreamCaptureStatus st = cudaStreamCaptureStatusNone;
    cudaStreamIsCapturing((cudaStream_t)0, &st);
    const bool capturing = (st != cudaStreamCaptureStatusNone);

    if (!capturing) {
        k_build_B<<<KP, MP>>>();
        if (!sync_check("build_B")) return;
        k_fold<<<(ROWS_P * KP + 255) / 256, 256>>>(x);
        if (!sync_check("fold")) return;
        k_gemm1<<<dim3(MP / 64, ROWS_P / 128), 256>>>();
        if (!sync_check("gemm1")) return;
        k_contract<<<dim3(NM, NSPL), 192, CT_SMEM_B>>>(w, out);
        if (!sync_check("contract")) return;
        return;
    }

    k_build_B<<<KP, MP>>>();
    k_fold<<<(ROWS_P * KP + 255) / 256, 256>>>(x);
    k_gemm1<<<dim3(MP / 64, ROWS_P / 128), 256>>>();
    k_contract<<<dim3(NM, NSPL), 192, CT_SMEM_B>>>(w, out);
}

// round 13
// speedup vs baseline: 1.0102x; 1.0102x over previous
#include <cuda_runtime.h>
#include <cstdint>
#include <cstdio>

// ----------------------------------------------------------------------------
// Real spherical harmonic transform -> real part (float32 out).
//   Re X[row,m] = sum_j E[row,j] * (s*cos(2pi m j/720)),  row = b*360+k
//   out[b,n,m]  = sum_k Re X[b,k,m] * W[m,n,k]
// R13: contract cp.async pipeline with ISSUE-BEFORE-COMPUTE ordering
// (2-phase in-flight window). Everything else = R12 (passing).
// ----------------------------------------------------------------------------

#define NTH   360
#define NLAM  720
#define NM    361
#define NB    8
#define ROWS  (NB*NTH) // 2880
#define ROWS_P 2944    // padded to multiple of 128
#define KP    368
#define MP    384

#define X_ELEMS (NB*NTH*NLAM)       // 2,073,600
#define W_ELEMS (NM*NTH*NTH)        // 46,785,600
#define OUT_ELEMS (NB*NTH*NM)       // 1,039,680 float32

__device__ float g_C  [KP * MP];        // [j][m] = s*cos(2pi m j / 720)
__device__ float g_E  [ROWS_P * KP];    // [row][j] even fold (pad rows zero)
__device__ float g_Xre[MP * ROWS_P];    // [m][row]
__device__ __align__(16) float g_zero4[4] = {0.f, 0.f, 0.f, 0.f};

// ---------------------------------------------------------------- ptx helpers
__device__ __forceinline__ uint32_t smem_u32(const void* p) {
    uint32_t a;
    asm("{ .reg .u64 t; cvta.to.shared.u64 t, %1; cvt.u32.u64 %0, t; }"
        : "=r"(a) : "l"(p));
    return a;
}
#define CP_ASYNC16(dst, src) \
    asm volatile("cp.async.cg.shared.global [%0], [%1], 16;" \
                 :: "r"(dst), "l"(src) : "memory")
#define CP_COMMIT()  asm volatile("cp.async.commit_group;" ::: "memory")
#define CP_WAIT1()   asm volatile("cp.async.wait_group 1;" ::: "memory")

// ---------------------------------------------------------------- build table
__global__ void k_build_B() {
    int l = blockIdx.x;          // 0..367
    int m = threadIdx.x;         // 0..383
    float vc = 0.f;
    if (l <= 360) {
        int p = (l * m) % 720;
        float c = cospif((float)p * (1.0f / 360.0f));
        vc = 0.008726646259971648f * c;      // 2*pi/720
    }
    g_C[l * MP + m] = vc;
}

// ---------------------------------------------------------------- fold E
__global__ void k_fold(const float* __restrict__ x) {
    int idx = blockIdx.x * blockDim.x + threadIdx.x;
    if (idx >= ROWS_P * KP) return;
    int r = idx / KP;
    int j = idx - r * KP;
    float e = 0.f;
    if (r < ROWS && j <= 360) {
        const float* xr = x + r * NLAM;
        if (j == 0)        e = xr[0];
        else if (j == 360) e = xr[360];
        else               e = xr[j] + xr[NLAM - j];
    }
    g_E[idx] = e;
}

// ---------------------------------------------------------------- GEMM1 (DFT)
// Xre[row,m] = sum_j E[row,j] * C[j,m].  BM=128, BN=64, BK=16, 256 threads.
#define EPAD 132
#define CPAD 68
__global__ void __launch_bounds__(256) k_gemm1() {
    __shared__ __align__(16) float sE[16 * EPAD];   // [kk][row(128)]
    __shared__ __align__(16) float sC[16 * CPAD];   // [kk][m(64)]

    const int tid = threadIdx.x;
    const int ty  = tid >> 4;         // 0..15 -> rows ty*8 .. ty*8+7
    const int tx  = tid & 15;         // 0..15 -> m tx*4 .. tx*4+3
    const int m0   = blockIdx.x * 64;
    const int row0 = blockIdx.y * 128;

    float acc[8][4];
#pragma unroll
    for (int i = 0; i < 8; ++i)
#pragma unroll
        for (int j = 0; j < 4; ++j) acc[i][j] = 0.f;

    for (int k0 = 0; k0 < KP; k0 += 16) {
#pragma unroll
        for (int t = 0; t < 2; ++t) {
            int i = tid + t * 256;        // 0..511
            int r = i >> 2;               // 0..127
            int q = i & 3;
            float4 v = *reinterpret_cast<const float4*>(
                &g_E[(row0 + r) * KP + k0 + 4 * q]);
            sE[(4 * q + 0) * EPAD + r] = v.x;
            sE[(4 * q + 1) * EPAD + r] = v.y;
            sE[(4 * q + 2) * EPAD + r] = v.z;
            sE[(4 * q + 3) * EPAD + r] = v.w;
        }
        {
            int kk = tid >> 4;
            int q  = tid & 15;
            float4 v = *reinterpret_cast<const float4*>(
                &g_C[(k0 + kk) * MP + m0 + 4 * q]);
            *reinterpret_cast<float4*>(&sC[kk * CPAD + 4 * q]) = v;
        }
        __syncthreads();
#pragma unroll
        for (int kk = 0; kk < 16; ++kk) {
            float4 e0 = *reinterpret_cast<const float4*>(&sE[kk * EPAD + ty * 8]);
            float4 e1 = *reinterpret_cast<const float4*>(&sE[kk * EPAD + ty * 8 + 4]);
            float4 c  = *reinterpret_cast<const float4*>(&sC[kk * CPAD + tx * 4]);
            float e[8] = {e0.x, e0.y, e0.z, e0.w, e1.x, e1.y, e1.z, e1.w};
            float cv[4] = {c.x, c.y, c.z, c.w};
#pragma unroll
            for (int i = 0; i < 8; ++i)
#pragma unroll
                for (int j = 0; j < 4; ++j)
                    acc[i][j] = fmaf(e[i], cv[j], acc[i][j]);
        }
        __syncthreads();
    }
#pragma unroll
    for (int j = 0; j < 4; ++j) {
        int m = m0 + tx * 4 + j;
        float4 v0 = make_float4(acc[0][j], acc[1][j], acc[2][j], acc[3][j]);
        float4 v1 = make_float4(acc[4][j], acc[5][j], acc[6][j], acc[7][j]);
        *reinterpret_cast<float4*>(&g_Xre[m * ROWS_P + row0 + ty * 8])     = v0;
        *reinterpret_cast<float4*>(&g_Xre[m * ROWS_P + row0 + ty * 8 + 4]) = v1;
    }
}

// ---------------------------------------------------------------- contraction
// Grid (361, 2): (m, n-half). 192 threads, thread t owns n=t (<180), 8 b.
// cp.async 3-stage pipeline; stage p+2 issued BEFORE computing stage p,
// giving each copy a ~2-phase in-flight window.
#define NSPL 2
#define NPB  (NTH / NSPL)          // 180
#define KC2  16
#define WST  20                    // conflict-free for quarter-warp LDS.128
#define NPH  ((NTH + KC2 - 1) / KC2)   // 23
#define XS_F (ROWS + KC2)          // 2896 floats
#define CT_SMEM_F (XS_F + 3 * NPB * WST)   // 2896 + 10800 = 13696 floats
#define CT_SMEM_B (CT_SMEM_F * 4)          // 54784 bytes

__global__ void __launch_bounds__(192) k_contract(const float* __restrict__ W,
                                                  float* __restrict__ out) {
    extern __shared__ __align__(16) float dyn[];
    float* Xs = dyn;                       // [XS_F]
    float* Ws = dyn + XS_F;                // [3][NPB*WST]

    const int m   = blockIdx.x;
    const int ys  = blockIdx.y;
    const int tid = threadIdx.x;
    const int n   = tid;
    const bool live = (n < NPB);

    const float* Wm = W + (size_t)m * (NTH * NTH) + (size_t)ys * NPB * NTH;
    const float* Xg = g_Xre + (size_t)m * ROWS_P;

    auto issue_stage = [&](int stage, int k0) {
        float* dstbase = Ws + stage * (NPB * WST);
#pragma unroll
        for (int u = 0; u < 4; ++u) {
            int i = tid + 192 * u;
            if (i < NPB * (KC2 / 4)) {
                int nl = i >> 2;
                int k  = k0 + (i & 3) * 4;
                const void* src = (k + 4 <= NTH)
                    ? (const void*)(Wm + (size_t)nl * NTH + k)
                    : (const void*)g_zero4;
                CP_ASYNC16(smem_u32(&dstbase[nl * WST + (i & 3) * 4]), src);
            }
        }
    };

    // prologue: Xs + stage0 -> group0 ; stage1 -> group1
#pragma unroll
    for (int u = 0; u < 4; ++u) {
        int i = tid + 192 * u;
        if (i < XS_F / 4) {
            const void* src = (4 * i + 4 <= ROWS)
                ? (const void*)(Xg + 4 * i)
                : (const void*)g_zero4;
            CP_ASYNC16(smem_u32(&Xs[4 * i]), src);
        }
    }
    issue_stage(0, 0);
    CP_COMMIT();
    issue_stage(1, KC2);
    CP_COMMIT();

    float acc[8];
#pragma unroll
    for (int b = 0; b < 8; ++b) acc[b] = 0.f;

    for (int p = 0; p < NPH; ++p) {
        CP_WAIT1();                  // stage p (group p) complete
        __syncthreads();             // all threads see stage p; buf (p+2)%3 free
        // EARLY ISSUE: stage p+2 starts its DRAM trip while we compute stage p
        if (p + 2 < NPH) issue_stage((p + 2) % 3, (p + 2) * KC2);
        CP_COMMIT();                 // always commit (keeps group numbering)

        const float* Wb = Ws + (p % 3) * (NPB * WST);
        const int k0 = p * KC2;
        if (live) {
#pragma unroll
            for (int q = 0; q < KC2 / 4; ++q) {
                float4 wv = *reinterpret_cast<const float4*>(&Wb[n * WST + 4 * q]);
#pragma unroll
                for (int b = 0; b < 8; ++b) {
                    float4 xv = *reinterpret_cast<const float4*>(
                        &Xs[b * NTH + k0 + 4 * q]);   // warp-broadcast
                    acc[b] = fmaf(xv.x, wv.x, acc[b]);
                    acc[b] = fmaf(xv.y, wv.y, acc[b]);
                    acc[b] = fmaf(xv.z, wv.z, acc[b]);
                    acc[b] = fmaf(xv.w, wv.w, acc[b]);
                }
            }
        }
    }

    if (live) {
        const int ng = ys * NPB + n;
#pragma unroll
        for (int b = 0; b < 8; ++b)
            out[(size_t)(b * NTH + ng) * NM + m] = acc[b];
    }
}

// ---------------------------------------------------------------- host diag
static bool sync_check(const char* stage) {
    cudaError_t e = cudaDeviceSynchronize();
    if (e == cudaSuccess) e = cudaGetLastError();
    if (e != cudaSuccess) {
        fprintf(stderr, "[diag] stage %-10s : %s\n", stage, cudaGetErrorString(e));
        fflush(stderr);
        return false;
    }
    return true;
}

// ---------------------------------------------------------------- launch
extern "C" void kernel_launch(void* const* d_in, const int* in_sizes, int n_in,
                              void* d_out, int out_size) {
    const float* x = nullptr;
    const float* w = nullptr;
    for (int i = 0; i < n_in; ++i) {
        if (in_sizes[i] == X_ELEMS && !x) x = (const float*)d_in[i];
        else if (in_sizes[i] == W_ELEMS && !w) w = (const float*)d_in[i];
    }
    float* out = (float*)d_out;
    if (!x || !w) return;

    cudaFuncSetAttribute(k_contract,
                         cudaFuncAttributeMaxDynamicSharedMemorySize, CT_SMEM_B);

    cudaStreamCaptureStatus st = cudaStreamCaptureStatusNone;
    cudaStreamIsCapturing((cudaStream_t)0, &st);
    const bool capturing = (st != cudaStreamCaptureStatusNone);

    if (!capturing) {
        k_build_B<<<KP, MP>>>();
        if (!sync_check("build_B")) return;
        k_fold<<<(ROWS_P * KP + 255) / 256, 256>>>(x);
        if (!sync_check("fold")) return;
        k_gemm1<<<dim3(MP / 64, ROWS_P / 128), 256>>>();
        if (!sync_check("gemm1")) return;
        k_contract<<<dim3(NM, NSPL), 192, CT_SMEM_B>>>(w, out);
        if (!sync_check("contract")) return;
        return;
    }

    k_build_B<<<KP, MP>>>();
    k_fold<<<(ROWS_P * KP + 255) / 256, 256>>>(x);
    k_gemm1<<<dim3(MP / 64, ROWS_P / 128), 256>>>();
    k_contract<<<dim3(NM, NSPL), 192, CT_SMEM_B>>>(w, out);
}